// round 15
// baseline (speedup 1.0000x reference)
#include <cuda_runtime.h>

// EfficientGCN preprocess on GB300 — pure-gmem float4-paired, GRID-RESIDENT.
// x: (N=128, C=3, T=300, V=25, M=2) fp32, conn: int32[25]
// out: (N, 3, 6, T, V, M) fp32
//
// 888 blocks (148 SM x 6 CTA) x 256 threads, fully resident; each thread
// grid-strides over the 480K float4-pair items (2-3 items each). This removes
// the 2.11-round occupancy-wave tail that capped all previous one-item-per-
// thread variants (~13us CTA duration quantized the drain).
// Per item: self/t+2 LDG.128, t+1 2xLDG.64, center/parent small L1-hit
// gathers, 18x STG.128 streaming stores. acos via A&S 4.4.46 minimax.

#define N_ 128
#define C_ 3
#define T_ 300
#define V_ 25
#define ROWF 50           // floats per t-row (V*M)
#define CSLAB 15000       // floats per channel slab (T*ROWF)
#define RPAIRS 150        // row-pairs per sequence (T/2)
#define NBLK 888          // 148 SMs x 6 resident CTAs
#define NTHR 256

__device__ __forceinline__ float acos_fast(float x)
{
    float ax = fabsf(x);
    float p = -0.0012624911f;
    p = fmaf(p, ax,  0.0066700901f);
    p = fmaf(p, ax, -0.0170881256f);
    p = fmaf(p, ax,  0.0308918810f);
    p = fmaf(p, ax, -0.0501743046f);
    p = fmaf(p, ax,  0.0889789874f);
    p = fmaf(p, ax, -0.2145988016f);
    p = fmaf(p, ax,  1.5707963050f);
    float r = sqrtf(1.0f - ax) * p;
    return (x >= 0.0f) ? r : (3.14159265358979f - r);
}

__device__ __forceinline__ void process_item(
    int q, const float* __restrict__ x, const int* __restrict__ conn,
    float* __restrict__ out)
{
    const int k   = q % 25;                  // float4 column 0..24
    const int nrp = q / 25;
    const int rp  = nrp % RPAIRS;            // row-pair 0..149
    const int n   = nrp / RPAIRS;

    // joints jA=2k, jB=2k+1 within the 100-float (2-row) segment
    const int dA = (k >= 13);
    const int dB = (k >= 12);
    const int rA = 2 * rp + dA;              // global t of joint A
    const int rB = 2 * rp + dB;
    const int vA = 2 * k     - V_ * dA;
    const int vB = 2 * k + 1 - V_ * dB;

    const int pvA = __ldg(&conn[vA]);
    const int pvB = __ldg(&conn[vB]);
    const float selA = (rA < T_ - 2) ? 1.0f : 0.0f;
    const float selB = (rB < T_ - 2) ? 1.0f : 0.0f;

    const int seg = 100 * rp + 4 * k;        // packed float4 offset in channel slab

    const float* xn = x + n * (C_ * CSLAB);
    float* ob = out + (size_t)n * 18 * CSLAB + seg;

    // clamp t+1/t+2 row offsets at the sequence end (results zeroed by sel)
    const int o1 = (2 * rp + 2 < T_) ? ROWF     : 0;
    const int o2 = (2 * rp + 2 < T_) ? 2 * ROWF : 0;

    float4 b[3];                             // bone vecs, live across channels

#pragma unroll
    for (int c = 0; c < C_; ++c) {
        const float* base = xn + c * CSLAB;

        float4 a    = *(const float4*)(base + seg);                // self (aligned)
        float2 n1lo = *(const float2*)(base + seg + o1);           // t+1
        float2 n1hi = *(const float2*)(base + seg + o1 + 2);
        float4 n2   = *(const float4*)(base + seg + o2);           // t+2 (aligned)

        float2 cA = ((const float2*)(base + rA * ROWF))[1];
        float2 cB = ((const float2*)(base + rB * ROWF))[1];
        float2 pA = ((const float2*)(base + rA * ROWF))[pvA];
        float2 pB = ((const float2*)(base + rB * ROWF))[pvB];

        __stcs((float4*)(ob + c * CSLAB), a);                                    // joint: x
        __stcs((float4*)(ob + (c + 3) * CSLAB),
               make_float4(a.x - cA.x, a.y - cA.y, a.z - cB.x, a.w - cB.y));     // x - center
        __stcs((float4*)(ob + (c + 6) * CSLAB),
               make_float4((n1lo.x - a.x) * selA, (n1lo.y - a.y) * selA,
                           (n1hi.x - a.z) * selB, (n1hi.y - a.w) * selB));       // v1
        __stcs((float4*)(ob + (c + 9) * CSLAB),
               make_float4((n2.x - a.x) * selA, (n2.y - a.y) * selA,
                           (n2.z - a.z) * selB, (n2.w - a.w) * selB));           // v2

        b[c] = make_float4(a.x - pA.x, a.y - pA.y, a.z - pB.x, a.w - pB.y);
        __stcs((float4*)(ob + (c + 12) * CSLAB), b[c]);                          // bone vec
    }

    // ---- bone angles ----
    float4 s = make_float4(
        b[0].x * b[0].x + b[1].x * b[1].x + b[2].x * b[2].x,
        b[0].y * b[0].y + b[1].y * b[1].y + b[2].y * b[2].y,
        b[0].z * b[0].z + b[1].z * b[1].z + b[2].z * b[2].z,
        b[0].w * b[0].w + b[1].w * b[1].w + b[2].w * b[2].w);
    float4 r = make_float4(__fdividef(1.0f, sqrtf(s.x) + 1e-4f),
                           __fdividef(1.0f, sqrtf(s.y) + 1e-4f),
                           __fdividef(1.0f, sqrtf(s.z) + 1e-4f),
                           __fdividef(1.0f, sqrtf(s.w) + 1e-4f));

#pragma unroll
    for (int c = 0; c < C_; ++c) {
        __stcs((float4*)(ob + (c + 15) * CSLAB),
               make_float4(acos_fast(b[c].x * r.x), acos_fast(b[c].y * r.y),
                           acos_fast(b[c].z * r.z), acos_fast(b[c].w * r.w)));   // bone angle
    }
}

__global__ __launch_bounds__(NTHR, 6) void egcn_preprocess_v10(
    const float* __restrict__ x,
    const int* __restrict__ conn,
    float* __restrict__ out)
{
    const int P = N_ * RPAIRS * 25;          // 480000 items
    const int stride = NBLK * NTHR;          // 227328 resident threads

    for (int q = blockIdx.x * NTHR + threadIdx.x; q < P; q += stride)
        process_item(q, x, conn, out);
}

extern "C" void kernel_launch(void* const* d_in, const int* in_sizes, int n_in,
                              void* d_out, int out_size)
{
    const float* x  = (const float*)d_in[0];
    const int* conn = (const int*)d_in[1];
    float* out      = (float*)d_out;

    egcn_preprocess_v10<<<NBLK, NTHR>>>(x, conn, out);
}